// round 1
// baseline (speedup 1.0000x reference)
#include <cuda_runtime.h>
#include <cuda_bf16.h>
#include <math.h>

// ---------------------------------------------------------------------------
// Problem constants: B=8, C=512, H=W=48 -> HW=2304; stride-2 conv -> 24x24=576
// ---------------------------------------------------------------------------
#define BATCH 8
#define CC    512
#define HH    48
#define WW    48
#define HWP   2304      // 48*48
#define HO    24
#define WO    24
#define PO    576       // 24*24
#define KIN   4608      // 512*9 (im2col K)

// scratch layout (floats)
#define OFF_COL    0L
#define SZ_COL     (8L*4608*576)          // 21,233,664
#define OFF_QC     (OFF_COL + SZ_COL)
#define SZ_QC      (8L*1024*576)          // 4,718,592
#define OFF_KC     (OFF_QC + SZ_QC)
#define SZ_KC      (8L*512*576)           // 2,359,296
#define OFF_EN     (OFF_KC + SZ_KC)
#define SZ_EN      (8L*1024*512)          // 4,194,304
#define OFF_QP     (OFF_EN + SZ_EN)
#define SZ_QP      (8L*64*2304)           // 1,179,648
#define OFF_KP     (OFF_QP + SZ_QP)
#define SZ_KP      (8L*64*2304)
#define OFF_AP     (OFF_KP + SZ_KP)
#define SZ_AP      (8L*2304*2304)         // 42,467,328
#define SZ_TOTAL   (OFF_AP + SZ_AP)       // 77,332,480 floats (~309 MB)

__device__ float g_scratch[SZ_TOTAL];

// ---------------------------------------------------------------------------
// im2col for 3x3 stride-2 pad-1 conv: col[b][ic*9+ky*3+kx][oy*24+ox]
// ---------------------------------------------------------------------------
__global__ void im2col_kernel(const float* __restrict__ x, float* __restrict__ col) {
    long idx = (long)blockIdx.x * 256 + threadIdx.x;
    const long total = 8L * KIN * PO;
    if (idx >= total) return;
    int p = (int)(idx % PO);
    long t = idx / PO;
    int r = (int)(t % KIN);
    int b = (int)(t / KIN);
    int ic = r / 9, k = r % 9;
    int ky = k / 3, kx = k % 3;
    int oy = p / WO, ox = p % WO;
    int iy = oy * 2 - 1 + ky;
    int ix = ox * 2 - 1 + kx;
    float v = 0.0f;
    if (iy >= 0 && iy < HH && ix >= 0 && ix < WW)
        v = x[((long)(b * CC + ic) * HH + iy) * WW + ix];
    col[idx] = v;
}

// ---------------------------------------------------------------------------
// Tiled fp32 GEMM.  MODE: 0=NN (A[M,K], B[K,N])  1=NT (A[M,K], B[N,K])
//                   2=TN (A[K,M], B[K,N])
// C[m,n] = sum_k opA(m,k)*opB(k,n) + (bias ? bias[m] : 0)
// Requirements used here: K % 8 == 0, N % 4 == 0, M % 4 == 0, leading dims
// divisible by 4 (all shapes in this problem satisfy these).
// ---------------------------------------------------------------------------
#define BM 128
#define BN 128
#define BK 8
#define TM 8
#define TN 8

template <int MODE>
__global__ __launch_bounds__(256, 2) void gemm_kernel(
    const float* __restrict__ A, const float* __restrict__ B,
    float* __restrict__ C, const float* __restrict__ bias,
    int M, int N, int K, long sA, long sB, long sC)
{
    __shared__ float As[BK][BM];
    __shared__ float Bs[BK][BN];

    int b = blockIdx.z;
    A += (long)b * sA;
    B += (long)b * sB;
    C += (long)b * sC;

    int m0 = blockIdx.y * BM;
    int n0 = blockIdx.x * BN;
    int tid = threadIdx.x;
    int tx = tid & 15;       // 0..15  -> n
    int ty = tid >> 4;       // 0..15  -> m

    float acc[TM][TN];
#pragma unroll
    for (int i = 0; i < TM; i++)
#pragma unroll
        for (int j = 0; j < TN; j++) acc[i][j] = 0.0f;

    for (int k0 = 0; k0 < K; k0 += BK) {
        // ---- load A tile -> As[k][m]
        if (MODE == 0 || MODE == 1) {
            // A row-major [M, K]
            int m = tid >> 1;
            int kk = (tid & 1) * 4;
            float4 v = make_float4(0.f, 0.f, 0.f, 0.f);
            if (m0 + m < M)
                v = *(const float4*)&A[(long)(m0 + m) * K + k0 + kk];
            As[kk + 0][m] = v.x; As[kk + 1][m] = v.y;
            As[kk + 2][m] = v.z; As[kk + 3][m] = v.w;
        } else {
            // TN: A row-major [K, M]
            int kk = tid >> 5;
            int m = (tid & 31) * 4;
            float4 v = make_float4(0.f, 0.f, 0.f, 0.f);
            if (m0 + m < M)
                v = *(const float4*)&A[(long)(k0 + kk) * M + m0 + m];
            *(float4*)&As[kk][m] = v;
        }
        // ---- load B tile -> Bs[k][n]
        if (MODE == 0 || MODE == 2) {
            // B row-major [K, N]
            int kk = tid >> 5;
            int n = (tid & 31) * 4;
            float4 v = make_float4(0.f, 0.f, 0.f, 0.f);
            if (n0 + n < N)
                v = *(const float4*)&B[(long)(k0 + kk) * N + n0 + n];
            *(float4*)&Bs[kk][n] = v;
        } else {
            // NT: B row-major [N, K]
            int n = tid >> 1;
            int kk = (tid & 1) * 4;
            float4 v = make_float4(0.f, 0.f, 0.f, 0.f);
            if (n0 + n < N)
                v = *(const float4*)&B[(long)(n0 + n) * K + k0 + kk];
            Bs[kk + 0][n] = v.x; Bs[kk + 1][n] = v.y;
            Bs[kk + 2][n] = v.z; Bs[kk + 3][n] = v.w;
        }
        __syncthreads();

#pragma unroll
        for (int k = 0; k < BK; k++) {
            float a_frag[TM], b_frag[TN];
#pragma unroll
            for (int i = 0; i < TM; i += 4)
                *(float4*)&a_frag[i] = *(float4*)&As[k][ty * TM + i];
#pragma unroll
            for (int j = 0; j < TN; j += 4)
                *(float4*)&b_frag[j] = *(float4*)&Bs[k][tx * TN + j];
#pragma unroll
            for (int i = 0; i < TM; i++)
#pragma unroll
                for (int j = 0; j < TN; j++)
                    acc[i][j] = fmaf(a_frag[i], b_frag[j], acc[i][j]);
        }
        __syncthreads();
    }

    // ---- epilogue
#pragma unroll
    for (int i = 0; i < TM; i++) {
        int m = m0 + ty * TM + i;
        if (m >= M) continue;
        float bv = bias ? bias[m] : 0.0f;
#pragma unroll
        for (int j = 0; j < TN; j += 4) {
            int n = n0 + tx * TN + j;
            if (n >= N) continue;
            float4 v;
            v.x = acc[i][j + 0] + bv;
            v.y = acc[i][j + 1] + bv;
            v.z = acc[i][j + 2] + bv;
            v.w = acc[i][j + 3] + bv;
            *(float4*)&C[(long)m * N + n] = v;
        }
    }
}

// ---------------------------------------------------------------------------
// CAM softmax: row length 512. softmax(max(e)-e) == exp(min(e)-e)/sum.
// One block (128 threads) per row, in-place.
// ---------------------------------------------------------------------------
__global__ void softmax_c_kernel(float* __restrict__ E) {
    const int L = 512;
    float* row = E + (long)blockIdx.x * L;
    int tid = threadIdx.x;  // 128 threads
    float vals[4];
    float mn = 3.4e38f;
#pragma unroll
    for (int c = 0; c < 4; c++) {
        vals[c] = row[tid + c * 128];
        mn = fminf(mn, vals[c]);
    }
#pragma unroll
    for (int o = 16; o; o >>= 1) mn = fminf(mn, __shfl_xor_sync(~0u, mn, o));
    __shared__ float shm[4];
    if ((tid & 31) == 0) shm[tid >> 5] = mn;
    __syncthreads();
    mn = fminf(fminf(shm[0], shm[1]), fminf(shm[2], shm[3]));

    float s = 0.0f;
#pragma unroll
    for (int c = 0; c < 4; c++) {
        vals[c] = __expf(mn - vals[c]);
        s += vals[c];
    }
#pragma unroll
    for (int o = 16; o; o >>= 1) s += __shfl_xor_sync(~0u, s, o);
    __shared__ float shs[4];
    if ((tid & 31) == 0) shs[tid >> 5] = s;
    __syncthreads();
    s = shs[0] + shs[1] + shs[2] + shs[3];
    float r = 1.0f / s;
#pragma unroll
    for (int c = 0; c < 4; c++) row[tid + c * 128] = vals[c] * r;
}

// ---------------------------------------------------------------------------
// PAM softmax: row length 2304, standard softmax, one block (256 thr) per row.
// ---------------------------------------------------------------------------
__global__ void softmax_p_kernel(float* __restrict__ E) {
    const int L = 2304;
    float* row = E + (long)blockIdx.x * L;
    int tid = threadIdx.x;  // 256 threads, 9 elems each
    float vals[9];
    float mx = -3.4e38f;
#pragma unroll
    for (int c = 0; c < 9; c++) {
        vals[c] = row[tid + c * 256];
        mx = fmaxf(mx, vals[c]);
    }
#pragma unroll
    for (int o = 16; o; o >>= 1) mx = fmaxf(mx, __shfl_xor_sync(~0u, mx, o));
    __shared__ float shm[8];
    if ((tid & 31) == 0) shm[tid >> 5] = mx;
    __syncthreads();
    mx = shm[0];
#pragma unroll
    for (int i = 1; i < 8; i++) mx = fmaxf(mx, shm[i]);

    float s = 0.0f;
#pragma unroll
    for (int c = 0; c < 9; c++) {
        vals[c] = __expf(vals[c] - mx);
        s += vals[c];
    }
#pragma unroll
    for (int o = 16; o; o >>= 1) s += __shfl_xor_sync(~0u, s, o);
    __shared__ float shs[8];
    if ((tid & 31) == 0) shs[tid >> 5] = s;
    __syncthreads();
    s = 0.0f;
#pragma unroll
    for (int i = 0; i < 8; i++) s += shs[i];
    float r = 1.0f / s;
#pragma unroll
    for (int c = 0; c < 9; c++) row[tid + c * 256] = vals[c] * r;
}

// ---------------------------------------------------------------------------
// Host side
// ---------------------------------------------------------------------------
static void launch_gemm(int mode, const float* A, const float* B, float* C,
                        const float* bias, int M, int N, int K,
                        long sA, long sB, long sC) {
    dim3 grid((N + BN - 1) / BN, (M + BM - 1) / BM, BATCH);
    switch (mode) {
        case 0: gemm_kernel<0><<<grid, 256>>>(A, B, C, bias, M, N, K, sA, sB, sC); break;
        case 1: gemm_kernel<1><<<grid, 256>>>(A, B, C, bias, M, N, K, sA, sB, sC); break;
        case 2: gemm_kernel<2><<<grid, 256>>>(A, B, C, bias, M, N, K, sA, sB, sC); break;
    }
}

extern "C" void kernel_launch(void* const* d_in, const int* in_sizes, int n_in,
                              void* d_out, int out_size) {
    const float* x   = (const float*)d_in[0];  // (8,512,48,48)
    const float* Wqc = (const float*)d_in[1];  // (1024,512,3,3)
    const float* bqc = (const float*)d_in[2];  // (1024,)
    const float* Wkc = (const float*)d_in[3];  // (512,512,3,3)
    const float* bkc = (const float*)d_in[4];  // (512,)
    const float* Wqp = (const float*)d_in[5];  // (64,512,1,1)
    const float* bqp = (const float*)d_in[6];  // (64,)
    const float* Wkp = (const float*)d_in[7];  // (64,512,1,1)
    const float* bkp = (const float*)d_in[8];  // (64,)

    void* sp = nullptr;
    cudaGetSymbolAddress(&sp, g_scratch);
    float* col    = (float*)sp + OFF_COL;
    float* qc     = (float*)sp + OFF_QC;
    float* kc     = (float*)sp + OFF_KC;
    float* energy = (float*)sp + OFF_EN;   // becomes attn_c in place
    float* qp     = (float*)sp + OFF_QP;
    float* kp     = (float*)sp + OFF_KP;
    float* attn_p = (float*)sp + OFF_AP;

    float* out_c = (float*)d_out;                       // (8,1024,2304)
    float* out_p = out_c + 8L * 1024 * 2304;            // (8,1024,48,48)

    // 1. im2col for the stride-2 3x3 convs
    {
        long total = 8L * KIN * PO;
        im2col_kernel<<<(unsigned)((total + 255) / 256), 256>>>(x, col);
    }
    // 2. qc = Wqc @ col + bqc   (M=1024, N=576, K=4608) per batch
    launch_gemm(0, Wqc, col, qc, bqc, 1024, PO, KIN, 0, (long)KIN * PO, 1024L * PO);
    // 3. kc = Wkc @ col + bkc   (M=512)
    launch_gemm(0, Wkc, col, kc, bkc, 512, PO, KIN, 0, (long)KIN * PO, 512L * PO);
    // 4. energy = qc @ kc^T     (M=1024, N=512, K=576)
    launch_gemm(1, qc, kc, energy, nullptr, 1024, 512, PO,
                1024L * PO, 512L * PO, 1024L * 512);
    // 5. attn_c = softmax(max-e) == exp(min-e)/sum, in place (8*1024 rows of 512)
    softmax_c_kernel<<<8 * 1024, 128>>>(energy);
    // 6. out_c = attn_c @ xf    (M=1024, N=2304, K=512)
    launch_gemm(0, energy, x, out_c, nullptr, 1024, HWP, 512,
                1024L * 512, (long)CC * HWP, 1024L * HWP);
    // 7. qp = Wqp @ xf + bqp    (M=64, N=2304, K=512)
    launch_gemm(0, Wqp, x, qp, bqp, 64, HWP, 512, 0, (long)CC * HWP, 64L * HWP);
    // 8. kp = Wkp @ xf + bkp
    launch_gemm(0, Wkp, x, kp, bkp, 64, HWP, 512, 0, (long)CC * HWP, 64L * HWP);
    // 9. energy_p = qp^T @ kp   (M=2304, N=2304, K=64)
    launch_gemm(2, qp, kp, attn_p, nullptr, HWP, HWP, 64,
                64L * HWP, 64L * HWP, (long)HWP * HWP);
    // 10. attn_p = softmax rows (8*2304 rows of 2304)
    softmax_p_kernel<<<8 * HWP, 256>>>(attn_p);
    // 11. out_p = out_c @ attn_p^T  (M=1024, N=2304, K=2304)
    launch_gemm(1, out_c, attn_p, out_p, nullptr, 1024, HWP, HWP,
                1024L * HWP, (long)HWP * HWP, 1024L * HWP);
}

// round 5
// speedup vs baseline: 1.7441x; 1.7441x over previous
#include <cuda_runtime.h>
#include <math.h>
#include <stdint.h>

// ---------------------------------------------------------------------------
// Problem: B=8, C=512, H=W=48 (HW=2304); stride-2 conv -> 24x24=576
// All GEMMs in NT form: C[M,N] = A[M,K] * B[N,K]^T, both operands K-major.
// Tensor path: mma.sync m16n8k8 tf32 with 3xTF32 error compensation:
//   x = hi + lo (hi = tf32(x), lo = tf32(x - hi))
//   A*B ~= Alo*Bhi + Ahi*Blo + Ahi*Bhi   (error ~2^-22, fp32-class)
// ---------------------------------------------------------------------------
#define BATCH 8

// scratch layout (floats)
#define OFF_COLT 0L
#define SZ_COLT  (8L*576*4608)
#define OFF_XT   (OFF_COLT + SZ_COLT)
#define SZ_XT    (8L*2304*512)
#define OFF_QC   (OFF_XT + SZ_XT)
#define SZ_QC    (8L*1024*576)
#define OFF_KC   (OFF_QC + SZ_QC)
#define SZ_KC    (8L*512*576)
#define OFF_EN   (OFF_KC + SZ_KC)
#define SZ_EN    (8L*1024*512)
#define OFF_QPT  (OFF_EN + SZ_EN)
#define SZ_QPT   (8L*2304*64)
#define OFF_KPT  (OFF_QPT + SZ_QPT)
#define SZ_KPT   (8L*2304*64)
#define OFF_AP   (OFF_KPT + SZ_KPT)
#define SZ_AP    (8L*2304*2304)
#define SZ_TOTAL (OFF_AP + SZ_AP)

__device__ float g_scratch[SZ_TOTAL];

// ---------------------------------------------------------------------------
// helpers
// ---------------------------------------------------------------------------
__device__ __forceinline__ uint32_t f2tf32(float f) {
    uint32_t u;
    asm("cvt.rna.tf32.f32 %0, %1;" : "=r"(u) : "f"(f));
    return u;
}
__device__ __forceinline__ void split_tf32(float f, uint32_t& hi, uint32_t& lo) {
    hi = f2tf32(f);
    lo = f2tf32(f - __uint_as_float(hi));
}
__device__ __forceinline__ void mma_tf32(float* d, const uint32_t* a, const uint32_t* b) {
    asm volatile(
        "mma.sync.aligned.m16n8k8.row.col.f32.tf32.tf32.f32 "
        "{%0,%1,%2,%3}, {%4,%5,%6,%7}, {%8,%9}, {%0,%1,%2,%3};"
        : "+f"(d[0]), "+f"(d[1]), "+f"(d[2]), "+f"(d[3])
        : "r"(a[0]), "r"(a[1]), "r"(a[2]), "r"(a[3]), "r"(b[0]), "r"(b[1]));
}

// ---------------------------------------------------------------------------
// NT GEMM via warp MMA + 3xTF32. Block 128x64x32, 128 threads (4 warps 2x2),
// warp tile 64x32 (4 m-frags x 4 n-frags of m16n8k8).
// SMEM rows padded to 36 floats -> conflict-free fragment loads.
// Requires M%128==0, N%64==0, K%32==0 (all shapes here comply).
// ---------------------------------------------------------------------------
#define GBM 128
#define GBN 64
#define GBK 32
#define LDSA 36
#define A_FLOATS (128 * LDSA)           // per stage
#define B_FLOATS (64 * LDSA)
#define SMEM_FLOATS (2 * A_FLOATS + 2 * B_FLOATS)
#define SMEM_BYTES (SMEM_FLOATS * 4)    // 55296

__global__ __launch_bounds__(128) void mma_gemm(
    const float* __restrict__ A, const float* __restrict__ B,
    float* __restrict__ C, const float* __restrict__ bias,
    int M, int N, int K, long sA, long sB, long sC, int bias_mode)
{
    extern __shared__ float sm[];
    float* As[2] = { sm, sm + A_FLOATS };
    float* Bs[2] = { sm + 2 * A_FLOATS, sm + 2 * A_FLOATS + B_FLOATS };

    const int tid = threadIdx.x;
    const int bz = blockIdx.z;
    A += (long)bz * sA;
    B += (long)bz * sB;
    C += (long)bz * sC;
    const int m0 = blockIdx.y * GBM;
    const int n0 = blockIdx.x * GBN;

    // ---- cp.async load mapping: 16B chunks. A: 128 rows x 8 chunks, B: 64 x 8.
    const int c8 = tid & 7;            // chunk col (16B units)
    const int r0 = tid >> 3;           // base row (16 threads stride)
    const float* gA = A + (long)(m0 + r0) * K + c8 * 4;
    const float* gB = B + (long)(n0 + r0) * K + c8 * 4;
    uint32_t sA0 = (uint32_t)__cvta_generic_to_shared(As[0] + r0 * LDSA + c8 * 4);
    uint32_t sA1 = (uint32_t)__cvta_generic_to_shared(As[1] + r0 * LDSA + c8 * 4);
    uint32_t sB0 = (uint32_t)__cvta_generic_to_shared(Bs[0] + r0 * LDSA + c8 * 4);
    uint32_t sB1 = (uint32_t)__cvta_generic_to_shared(Bs[1] + r0 * LDSA + c8 * 4);

    const int NT = K / GBK;

    // warp/lane decomposition
    const int warp = tid >> 5, lane = tid & 31;
    const int wm = (warp & 1) * 64;     // 2 warps in M
    const int wn = (warp >> 1) * 32;    // 2 warps in N
    const int gid = lane >> 2, tg = lane & 3;

    float acc[4][4][4];
#pragma unroll
    for (int i = 0; i < 4; i++)
#pragma unroll
        for (int j = 0; j < 4; j++)
#pragma unroll
            for (int c = 0; c < 4; c++) acc[i][j][c] = 0.0f;

    // ---- prologue: stage 0
    {
#pragma unroll
        for (int i = 0; i < 8; i++)
            asm volatile("cp.async.cg.shared.global [%0], [%1], 16;"
                         :: "r"(sA0 + i * 16 * LDSA * 4), "l"(gA + (long)i * 16 * K) : "memory");
#pragma unroll
        for (int i = 0; i < 4; i++)
            asm volatile("cp.async.cg.shared.global [%0], [%1], 16;"
                         :: "r"(sB0 + i * 16 * LDSA * 4), "l"(gB + (long)i * 16 * K) : "memory");
        asm volatile("cp.async.commit_group;" ::: "memory");
    }

    for (int kt = 0; kt < NT; kt++) {
        asm volatile("cp.async.wait_group 0;" ::: "memory");
        __syncthreads();

        if (kt + 1 < NT) {
            const long koff = (long)(kt + 1) * GBK;
            const uint32_t dA = ((kt + 1) & 1) ? sA1 : sA0;
            const uint32_t dB = ((kt + 1) & 1) ? sB1 : sB0;
#pragma unroll
            for (int i = 0; i < 8; i++)
                asm volatile("cp.async.cg.shared.global [%0], [%1], 16;"
                             :: "r"(dA + i * 16 * LDSA * 4), "l"(gA + koff + (long)i * 16 * K) : "memory");
#pragma unroll
            for (int i = 0; i < 4; i++)
                asm volatile("cp.async.cg.shared.global [%0], [%1], 16;"
                             :: "r"(dB + i * 16 * LDSA * 4), "l"(gB + koff + (long)i * 16 * K) : "memory");
            asm volatile("cp.async.commit_group;" ::: "memory");
        }

        const float* as = As[kt & 1];
        const float* bs = Bs[kt & 1];
#pragma unroll
        for (int ks = 0; ks < 4; ks++) {
            const int k0 = ks * 8;
            uint32_t ah[4][4], al[4][4], bh[4][2], bl[4][2];
#pragma unroll
            for (int i = 0; i < 4; i++) {
                const float* ap = as + (wm + i * 16 + gid) * LDSA + k0 + tg;
                split_tf32(ap[0],            ah[i][0], al[i][0]);
                split_tf32(ap[4],            ah[i][2], al[i][2]);
                split_tf32(ap[8 * LDSA],     ah[i][1], al[i][1]);
                split_tf32(ap[8 * LDSA + 4], ah[i][3], al[i][3]);
            }
#pragma unroll
            for (int j = 0; j < 4; j++) {
                const float* bp = bs + (wn + j * 8 + gid) * LDSA + k0 + tg;
                split_tf32(bp[0], bh[j][0], bl[j][0]);
                split_tf32(bp[4], bh[j][1], bl[j][1]);
            }
#pragma unroll
            for (int i = 0; i < 4; i++)
#pragma unroll
                for (int j = 0; j < 4; j++) {
                    mma_tf32(acc[i][j], al[i], bh[j]);
                    mma_tf32(acc[i][j], ah[i], bl[j]);
                    mma_tf32(acc[i][j], ah[i], bh[j]);
                }
        }
    }

    // ---- epilogue: c0,c1 -> (row, 2tg..2tg+1); c2,c3 -> (row+8, ...)
#pragma unroll
    for (int i = 0; i < 4; i++) {
        const int row = m0 + wm + i * 16 + gid;
        float bv0 = 0.f, bv8 = 0.f;
        if (bias_mode == 1) { bv0 = bias[row]; bv8 = bias[row + 8]; }
#pragma unroll
        for (int j = 0; j < 4; j++) {
            const int col = n0 + wn + j * 8 + tg * 2;
            float c0 = acc[i][j][0], c1 = acc[i][j][1];
            float c2 = acc[i][j][2], c3 = acc[i][j][3];
            if (bias_mode == 1) { c0 += bv0; c1 += bv0; c2 += bv8; c3 += bv8; }
            else if (bias_mode == 2) {
                float b0 = bias[col], b1 = bias[col + 1];
                c0 += b0; c1 += b1; c2 += b0; c3 += b1;
            }
            *(float2*)&C[(long)row * N + col] = make_float2(c0, c1);
            *(float2*)&C[(long)(row + 8) * N + col] = make_float2(c2, c3);
        }
    }
}

// ---------------------------------------------------------------------------
// im2col transposed: colT[b][p][ic*9+ky*3+kx], p in 24x24, stride2 pad1
// ---------------------------------------------------------------------------
__global__ void im2colT_kernel(const float* __restrict__ x, float* __restrict__ colT) {
    long idx = (long)blockIdx.x * 256 + threadIdx.x;
    const long total = 8L * 576 * 4608;
    if (idx >= total) return;
    int r = (int)(idx % 4608);
    long t = idx / 4608;
    int p = (int)(t % 576);
    int b = (int)(t / 576);
    int ic = r / 9, k = r % 9;
    int ky = k / 3, kx = k % 3;
    int oy = p / 24, ox = p % 24;
    int iy = oy * 2 - 1 + ky;
    int ix = ox * 2 - 1 + kx;
    float v = 0.0f;
    if ((unsigned)iy < 48u && (unsigned)ix < 48u)
        v = x[((long)(b * 512 + ic) * 48 + iy) * 48 + ix];
    colT[idx] = v;
}

// ---------------------------------------------------------------------------
// x transpose: xT[b][p][c] = x[b][c][p]
// ---------------------------------------------------------------------------
__global__ void transpose_x_kernel(const float* __restrict__ x, float* __restrict__ xT) {
    __shared__ float t[32][33];
    int b = blockIdx.z;
    int p0 = blockIdx.x * 32, c0 = blockIdx.y * 32;
    const float* xb = x + (long)b * 512 * 2304;
    float* ob = xT + (long)b * 2304 * 512;
    int tx = threadIdx.x, ty = threadIdx.y;   // (32, 8)
#pragma unroll
    for (int j = 0; j < 32; j += 8)
        t[ty + j][tx] = xb[(long)(c0 + ty + j) * 2304 + p0 + tx];
    __syncthreads();
#pragma unroll
    for (int j = 0; j < 32; j += 8)
        ob[(long)(p0 + ty + j) * 512 + c0 + tx] = t[tx][ty + j];
}

// ---------------------------------------------------------------------------
// CAM softmax: rows of 512. softmax(max(e)-e) == exp(min(e)-e)/sum.
// ---------------------------------------------------------------------------
__global__ void softmax_c_kernel(float* __restrict__ E) {
    float* row = E + (long)blockIdx.x * 512;
    int tid = threadIdx.x;  // 128
    float vals[4];
    float mn = 3.4e38f;
#pragma unroll
    for (int c = 0; c < 4; c++) {
        vals[c] = row[tid + c * 128];
        mn = fminf(mn, vals[c]);
    }
#pragma unroll
    for (int o = 16; o; o >>= 1) mn = fminf(mn, __shfl_xor_sync(~0u, mn, o));
    __shared__ float shm[4];
    if ((tid & 31) == 0) shm[tid >> 5] = mn;
    __syncthreads();
    mn = fminf(fminf(shm[0], shm[1]), fminf(shm[2], shm[3]));
    float s = 0.0f;
#pragma unroll
    for (int c = 0; c < 4; c++) {
        vals[c] = __expf(mn - vals[c]);
        s += vals[c];
    }
#pragma unroll
    for (int o = 16; o; o >>= 1) s += __shfl_xor_sync(~0u, s, o);
    __shared__ float shs[4];
    if ((tid & 31) == 0) shs[tid >> 5] = s;
    __syncthreads();
    s = shs[0] + shs[1] + shs[2] + shs[3];
    float r = 1.0f / s;
#pragma unroll
    for (int c = 0; c < 4; c++) row[tid + c * 128] = vals[c] * r;
}

// ---------------------------------------------------------------------------
// PAM softmax: rows of 2304
// ---------------------------------------------------------------------------
__global__ void softmax_p_kernel(float* __restrict__ E) {
    float* row = E + (long)blockIdx.x * 2304;
    int tid = threadIdx.x;  // 256
    float vals[9];
    float mx = -3.4e38f;
#pragma unroll
    for (int c = 0; c < 9; c++) {
        vals[c] = row[tid + c * 256];
        mx = fmaxf(mx, vals[c]);
    }
#pragma unroll
    for (int o = 16; o; o >>= 1) mx = fmaxf(mx, __shfl_xor_sync(~0u, mx, o));
    __shared__ float shm[8];
    if ((tid & 31) == 0) shm[tid >> 5] = mx;
    __syncthreads();
    mx = shm[0];
#pragma unroll
    for (int i = 1; i < 8; i++) mx = fmaxf(mx, shm[i]);
    float s = 0.0f;
#pragma unroll
    for (int c = 0; c < 9; c++) {
        vals[c] = __expf(vals[c] - mx);
        s += vals[c];
    }
#pragma unroll
    for (int o = 16; o; o >>= 1) s += __shfl_xor_sync(~0u, s, o);
    __shared__ float shs[8];
    if ((tid & 31) == 0) shs[tid >> 5] = s;
    __syncthreads();
    s = 0.0f;
#pragma unroll
    for (int i = 0; i < 8; i++) s += shs[i];
    float r = 1.0f / s;
#pragma unroll
    for (int c = 0; c < 9; c++) row[tid + c * 256] = vals[c] * r;
}

// ---------------------------------------------------------------------------
// Host
// ---------------------------------------------------------------------------
static void launch_mma_gemm(const float* A, const float* B, float* C, const float* bias,
                            int M, int N, int K, long sA, long sB, long sC, int bias_mode) {
    dim3 g(N / GBN, M / GBM, BATCH);
    mma_gemm<<<g, 128, SMEM_BYTES>>>(A, B, C, bias, M, N, K, sA, sB, sC, bias_mode);
}

extern "C" void kernel_launch(void* const* d_in, const int* in_sizes, int n_in,
                              void* d_out, int out_size) {
    const float* x   = (const float*)d_in[0];
    const float* Wqc = (const float*)d_in[1];
    const float* bqc = (const float*)d_in[2];
    const float* Wkc = (const float*)d_in[3];
    const float* bkc = (const float*)d_in[4];
    const float* Wqp = (const float*)d_in[5];
    const float* bqp = (const float*)d_in[6];
    const float* Wkp = (const float*)d_in[7];
    const float* bkp = (const float*)d_in[8];

    cudaFuncSetAttribute(mma_gemm, cudaFuncAttributeMaxDynamicSharedMemorySize, SMEM_BYTES);

    void* sp = nullptr;
    cudaGetSymbolAddress(&sp, g_scratch);
    float* colT   = (float*)sp + OFF_COLT;
    float* xT     = (float*)sp + OFF_XT;
    float* qc     = (float*)sp + OFF_QC;
    float* kc     = (float*)sp + OFF_KC;
    float* energy = (float*)sp + OFF_EN;
    float* qpT    = (float*)sp + OFF_QPT;
    float* kpT    = (float*)sp + OFF_KPT;
    float* attn_p = (float*)sp + OFF_AP;

    float* out_c = (float*)d_out;                 // (8,1024,2304)
    float* out_p = out_c + 8L * 1024 * 2304;      // (8,1024,48,48)

    // 1. layout passes
    {
        long total = 8L * 576 * 4608;
        im2colT_kernel<<<(unsigned)((total + 255) / 256), 256>>>(x, colT);
    }
    transpose_x_kernel<<<dim3(72, 16, 8), dim3(32, 8)>>>(x, xT);

    // 2. qc = Wqc * colT^T + bqc        (M=1024, N=576, K=4608)
    launch_mma_gemm(Wqc, colT, qc, bqc, 1024, 576, 4608, 0, 576L * 4608, 1024L * 576, 1);
    // 3. kc = Wkc * colT^T + bkc        (M=512)
    launch_mma_gemm(Wkc, colT, kc, bkc, 512, 576, 4608, 0, 576L * 4608, 512L * 576, 1);
    // 4. energy = qc * kc^T             (M=1024, N=512, K=576)
    launch_mma_gemm(qc, kc, energy, nullptr, 1024, 512, 576,
                    1024L * 576, 512L * 576, 1024L * 512, 0);
    // 5. attn_c = exp(min-e)/sum, in place
    softmax_c_kernel<<<8 * 1024, 128>>>(energy);
    // 6. out_c = attn_c * xT^T          (M=1024, N=2304, K=512)
    launch_mma_gemm(energy, xT, out_c, nullptr, 1024, 2304, 512,
                    1024L * 512, 2304L * 512, 1024L * 2304, 0);
    // 7. qpT = xT * Wqp^T + bqp[col]    (M=2304, N=64, K=512)
    launch_mma_gemm(xT, Wqp, qpT, bqp, 2304, 64, 512, 2304L * 512, 0, 2304L * 64, 2);
    // 8. kpT
    launch_mma_gemm(xT, Wkp, kpT, bkp, 2304, 64, 512, 2304L * 512, 0, 2304L * 64, 2);
    // 9. energy_p = qpT * kpT^T         (M=2304, N=2304, K=64)
    launch_mma_gemm(qpT, kpT, attn_p, nullptr, 2304, 2304, 64,
                    2304L * 64, 2304L * 64, 2304L * 2304, 0);
    // 10. row softmax
    softmax_p_kernel<<<8 * 2304, 256>>>(attn_p);
    // 11. out_p = out_c * attn_p^T      (M=1024, N=2304, K=2304)
    launch_mma_gemm(out_c, attn_p, out_p, nullptr, 1024, 2304, 2304,
                    1024L * 2304, 2304L * 2304, 1024L * 2304, 0);
}